// round 1
// baseline (speedup 1.0000x reference)
#include <cuda_runtime.h>

#define B_SZ  64
#define N_SZ  1024
#define IN_D  512
#define HID_D 1024
#define LAT_D 256

// Scratch (device globals — no allocation allowed)
__device__ float g_d[B_SZ * N_SZ];                         // 256 KB: D^{-1/2}
__device__ float g_h[(size_t)B_SZ * N_SZ * IN_D];          // 134 MB: a_norm @ x
__device__ float g_h1[(size_t)B_SZ * N_SZ * HID_D];        // 268 MB: relu(h@W1^T+b1)

// ---------------------------------------------------------------------------
// Kernel 1: d[b,i] = rsqrt(sum_j a[b,i,j] + 1 + 1e-8)   (one warp per row)
// ---------------------------------------------------------------------------
__global__ void __launch_bounds__(256) deg_kernel(const float* __restrict__ a) {
    int warp = (blockIdx.x * 256 + threadIdx.x) >> 5;      // 0 .. B*N-1 (grid exact)
    int lane = threadIdx.x & 31;
    const float4* row = (const float4*)(a + (size_t)warp * N_SZ);
    float s = 0.f;
#pragma unroll
    for (int j = 0; j < (N_SZ / 4) / 32; j++) {
        float4 v = row[lane + j * 32];
        s += v.x + v.y + v.z + v.w;
    }
#pragma unroll
    for (int off = 16; off; off >>= 1) s += __shfl_xor_sync(0xffffffffu, s, off);
    if (lane == 0) g_d[warp] = rsqrtf(s + 1.0f + 1e-8f);
}

// ---------------------------------------------------------------------------
// Kernel 2: h[b,i,c] = d_i * (sum_j a[b,i,j] * d_j * x[b,j,c]) + d_i^2 * x[b,i,c]
// BM=128, BN=128, BK=8, 8x8 per thread, 256 threads, double-buffered SMEM.
// ---------------------------------------------------------------------------
__global__ void __launch_bounds__(256) mp_kernel(const float* __restrict__ A,
                                                 const float* __restrict__ X) {
    const int b    = blockIdx.z;
    const int row0 = blockIdx.y * 128;
    const int col0 = blockIdx.x * 128;
    const float* Ab = A + (size_t)b * N_SZ * N_SZ;
    const float* Xb = X + (size_t)b * N_SZ * IN_D;
    const float* db = g_d + b * N_SZ;
    float*       Hb = g_h + (size_t)b * N_SZ * IN_D;

    __shared__ float As[2][8][128];   // [k][m]
    __shared__ float Bs[2][8][128];   // [k][n]

    const int tid  = threadIdx.x;
    const int tx   = tid & 15;        // 16 col groups
    const int ty   = tid >> 4;        // 16 row groups
    const int a_row = tid >> 1;       // A: row within tile
    const int a_k   = (tid & 1) * 4;  // A: k offset (float4)
    const int b_k   = tid >> 5;       // B: k row
    const int b_c   = (tid & 31) * 4; // B: col offset (float4)

    float acc[8][8] = {};

    // prologue: stage tile 0
    {
        float4 va = *(const float4*)(Ab + (size_t)(row0 + a_row) * N_SZ + a_k);
        As[0][a_k + 0][a_row] = va.x;
        As[0][a_k + 1][a_row] = va.y;
        As[0][a_k + 2][a_row] = va.z;
        As[0][a_k + 3][a_row] = va.w;
        float  dj = db[b_k];
        float4 vb = *(const float4*)(Xb + (size_t)b_k * IN_D + col0 + b_c);
        vb.x *= dj; vb.y *= dj; vb.z *= dj; vb.w *= dj;
        *(float4*)&Bs[0][b_k][b_c] = vb;
    }
    __syncthreads();

    int buf = 0;
    const int NT = N_SZ / 8;          // 128 k-tiles
    for (int t = 0; t < NT; t++) {
        float4 va, vb; float dj;
        const bool nxt = (t + 1 < NT);
        if (nxt) {
            int kt = (t + 1) * 8;
            va = *(const float4*)(Ab + (size_t)(row0 + a_row) * N_SZ + kt + a_k);
            dj = db[kt + b_k];
            vb = *(const float4*)(Xb + (size_t)(kt + b_k) * IN_D + col0 + b_c);
        }
#pragma unroll
        for (int k = 0; k < 8; k++) {
            float af[8], bf[8];
            *(float4*)(af)     = *(const float4*)&As[buf][k][ty * 8];
            *(float4*)(af + 4) = *(const float4*)&As[buf][k][ty * 8 + 4];
            *(float4*)(bf)     = *(const float4*)&Bs[buf][k][tx * 8];
            *(float4*)(bf + 4) = *(const float4*)&Bs[buf][k][tx * 8 + 4];
#pragma unroll
            for (int i = 0; i < 8; i++)
#pragma unroll
                for (int j = 0; j < 8; j++)
                    acc[i][j] = fmaf(af[i], bf[j], acc[i][j]);
        }
        if (nxt) {
            int nb = buf ^ 1;
            As[nb][a_k + 0][a_row] = va.x;
            As[nb][a_k + 1][a_row] = va.y;
            As[nb][a_k + 2][a_row] = va.z;
            As[nb][a_k + 3][a_row] = va.w;
            vb.x *= dj; vb.y *= dj; vb.z *= dj; vb.w *= dj;
            *(float4*)&Bs[nb][b_k][b_c] = vb;
            __syncthreads();
            buf = nb;
        }
    }

    // epilogue: scale by d_i, add diagonal (self-loop) term d_i^2 * x[i,c]
#pragma unroll
    for (int i = 0; i < 8; i++) {
        int   r  = row0 + ty * 8 + i;
        float di = db[r];
        float d2 = di * di;
#pragma unroll
        for (int j = 0; j < 8; j += 4) {
            int    c  = col0 + tx * 8 + j;
            float4 xv = *(const float4*)(Xb + (size_t)r * IN_D + c);
            float4 o;
            o.x = di * acc[i][j + 0] + d2 * xv.x;
            o.y = di * acc[i][j + 1] + d2 * xv.y;
            o.z = di * acc[i][j + 2] + d2 * xv.z;
            o.w = di * acc[i][j + 3] + d2 * xv.w;
            *(float4*)(Hb + (size_t)r * IN_D + c) = o;
        }
    }
}

// ---------------------------------------------------------------------------
// FC core: out[m,n] = act( sum_k Ain[m,k]*W[n,k] + bias[n] )
// Both A and W are K-major -> both tiles staged with transposed stores.
// ---------------------------------------------------------------------------
template <int K, int LDO, bool RELU>
__device__ __forceinline__ void fc_core(const float* __restrict__ Ain,
                                        const float* __restrict__ W,
                                        const float* __restrict__ bias,
                                        float* __restrict__ out) {
    const int row0 = blockIdx.y * 128;
    const int col0 = blockIdx.x * 128;

    __shared__ float As[2][8][128];
    __shared__ float Bs[2][8][128];

    const int tid   = threadIdx.x;
    const int tx    = tid & 15;
    const int ty    = tid >> 4;
    const int l_row = tid >> 1;
    const int l_k   = (tid & 1) * 4;

    float acc[8][8] = {};

    {
        float4 va = *(const float4*)(Ain + (size_t)(row0 + l_row) * K + l_k);
        As[0][l_k + 0][l_row] = va.x;
        As[0][l_k + 1][l_row] = va.y;
        As[0][l_k + 2][l_row] = va.z;
        As[0][l_k + 3][l_row] = va.w;
        float4 vb = *(const float4*)(W + (size_t)(col0 + l_row) * K + l_k);
        Bs[0][l_k + 0][l_row] = vb.x;
        Bs[0][l_k + 1][l_row] = vb.y;
        Bs[0][l_k + 2][l_row] = vb.z;
        Bs[0][l_k + 3][l_row] = vb.w;
    }
    __syncthreads();

    int buf = 0;
    const int NT = K / 8;
    for (int t = 0; t < NT; t++) {
        float4 va, vb;
        const bool nxt = (t + 1 < NT);
        if (nxt) {
            int kt = (t + 1) * 8;
            va = *(const float4*)(Ain + (size_t)(row0 + l_row) * K + kt + l_k);
            vb = *(const float4*)(W   + (size_t)(col0 + l_row) * K + kt + l_k);
        }
#pragma unroll
        for (int k = 0; k < 8; k++) {
            float af[8], bf[8];
            *(float4*)(af)     = *(const float4*)&As[buf][k][ty * 8];
            *(float4*)(af + 4) = *(const float4*)&As[buf][k][ty * 8 + 4];
            *(float4*)(bf)     = *(const float4*)&Bs[buf][k][tx * 8];
            *(float4*)(bf + 4) = *(const float4*)&Bs[buf][k][tx * 8 + 4];
#pragma unroll
            for (int i = 0; i < 8; i++)
#pragma unroll
                for (int j = 0; j < 8; j++)
                    acc[i][j] = fmaf(af[i], bf[j], acc[i][j]);
        }
        if (nxt) {
            int nb = buf ^ 1;
            As[nb][l_k + 0][l_row] = va.x;
            As[nb][l_k + 1][l_row] = va.y;
            As[nb][l_k + 2][l_row] = va.z;
            As[nb][l_k + 3][l_row] = va.w;
            Bs[nb][l_k + 0][l_row] = vb.x;
            Bs[nb][l_k + 1][l_row] = vb.y;
            Bs[nb][l_k + 2][l_row] = vb.z;
            Bs[nb][l_k + 3][l_row] = vb.w;
            __syncthreads();
            buf = nb;
        }
    }

    float bj[8];
#pragma unroll
    for (int j = 0; j < 8; j++) bj[j] = bias[col0 + tx * 8 + j];

#pragma unroll
    for (int i = 0; i < 8; i++) {
        int r = row0 + ty * 8 + i;
#pragma unroll
        for (int j = 0; j < 8; j += 4) {
            int    c = col0 + tx * 8 + j;
            float4 o;
            o.x = acc[i][j + 0] + bj[j + 0];
            o.y = acc[i][j + 1] + bj[j + 1];
            o.z = acc[i][j + 2] + bj[j + 2];
            o.w = acc[i][j + 3] + bj[j + 3];
            if (RELU) {
                o.x = fmaxf(o.x, 0.f); o.y = fmaxf(o.y, 0.f);
                o.z = fmaxf(o.z, 0.f); o.w = fmaxf(o.w, 0.f);
            }
            *(float4*)(out + (size_t)r * LDO + c) = o;
        }
    }
}

__global__ void __launch_bounds__(256) fc1_kernel(const float* __restrict__ W1,
                                                  const float* __restrict__ b1) {
    fc_core<IN_D, HID_D, true>(g_h, W1, b1, g_h1);
}

__global__ void __launch_bounds__(256) fc2_kernel(const float* __restrict__ W,
                                                  const float* __restrict__ bias,
                                                  float* __restrict__ out) {
    fc_core<HID_D, LAT_D, false>(g_h1, W, bias, out);
}

// ---------------------------------------------------------------------------
extern "C" void kernel_launch(void* const* d_in, const int* in_sizes, int n_in,
                              void* d_out, int out_size) {
    const float* x   = (const float*)d_in[0];
    const float* a   = (const float*)d_in[1];
    const float* W1  = (const float*)d_in[2];
    const float* b1  = (const float*)d_in[3];
    const float* Wmu = (const float*)d_in[4];
    const float* bmu = (const float*)d_in[5];
    const float* Wlv = (const float*)d_in[6];
    const float* blv = (const float*)d_in[7];
    float* out = (float*)d_out;

    // 1) degree / normalization factors
    deg_kernel<<<(B_SZ * N_SZ) / 8, 256>>>(a);

    // 2) message passing: h = a_norm @ x   (normalization fused)
    mp_kernel<<<dim3(IN_D / 128, N_SZ / 128, B_SZ), 256>>>(a, x);

    // 3) h1 = relu(h @ W1^T + b1)
    fc1_kernel<<<dim3(HID_D / 128, (B_SZ * N_SZ) / 128), 256>>>(W1, b1);

    // 4) mu / logvar heads
    fc2_kernel<<<dim3(LAT_D / 128, (B_SZ * N_SZ) / 128), 256>>>(Wmu, bmu, out);
    fc2_kernel<<<dim3(LAT_D / 128, (B_SZ * N_SZ) / 128), 256>>>(
        Wlv, blv, out + (size_t)B_SZ * N_SZ * LAT_D);
}

// round 3
// speedup vs baseline: 2.2989x; 2.2989x over previous
#include <cuda_runtime.h>
#include <cuda_bf16.h>
#include <cstdint>

#define BB    64
#define NNODE 1024
#define IND   512
#define HIDD  1024
#define LATD  256
#define TOK   (BB * NNODE)   // 65536

// ---------------------------------------------------------------------------
// Scratch (device globals — allocation is forbidden)
// ---------------------------------------------------------------------------
__device__ float g_d[TOK];
__device__ __align__(16) __nv_bfloat16 g_ahi[(size_t)BB * NNODE * NNODE];
__device__ __align__(16) __nv_bfloat16 g_alo[(size_t)BB * NNODE * NNODE];
__device__ __align__(16) __nv_bfloat16 g_xthi[(size_t)BB * IND * NNODE];
__device__ __align__(16) __nv_bfloat16 g_xtlo[(size_t)BB * IND * NNODE];
__device__ __align__(16) __nv_bfloat16 g_hhi[(size_t)TOK * IND];
__device__ __align__(16) __nv_bfloat16 g_hlo[(size_t)TOK * IND];
__device__ __align__(16) __nv_bfloat16 g_h1hi[(size_t)TOK * HIDD];
__device__ __align__(16) __nv_bfloat16 g_h1lo[(size_t)TOK * HIDD];
__device__ __align__(16) __nv_bfloat16 g_w1hi[HIDD * IND],  g_w1lo[HIDD * IND];
__device__ __align__(16) __nv_bfloat16 g_wmuhi[LATD * HIDD], g_wmulo[LATD * HIDD];
__device__ __align__(16) __nv_bfloat16 g_wlvhi[LATD * HIDD], g_wlvlo[LATD * HIDD];

// ---------------------------------------------------------------------------
// helpers (baseline PTX only — no sm_103a-gated features)
// ---------------------------------------------------------------------------
__device__ __forceinline__ uint32_t smem_u32(const void* p) {
    uint32_t a;
    asm("{ .reg .u64 t; cvta.to.shared.u64 t, %1; cvt.u32.u64 %0, t; }" : "=r"(a) : "l"(p));
    return a;
}
__device__ __forceinline__ void ldsm4(uint32_t addr, uint32_t* r) {
    asm volatile("ldmatrix.sync.aligned.m8n8.x4.shared.b16 {%0,%1,%2,%3}, [%4];"
                 : "=r"(r[0]), "=r"(r[1]), "=r"(r[2]), "=r"(r[3]) : "r"(addr));
}
__device__ __forceinline__ void mma16816(float* c, const uint32_t* a, const uint32_t* b) {
    asm volatile(
        "mma.sync.aligned.m16n8k16.row.col.f32.bf16.bf16.f32 "
        "{%0,%1,%2,%3}, {%4,%5,%6,%7}, {%8,%9}, {%0,%1,%2,%3};"
        : "+f"(c[0]), "+f"(c[1]), "+f"(c[2]), "+f"(c[3])
        : "r"(a[0]), "r"(a[1]), "r"(a[2]), "r"(a[3]), "r"(b[0]), "r"(b[1]));
}

// ---------------------------------------------------------------------------
// Kernel: degree -> d = rsqrt(sum_j a_ij + 1 + 1e-8)
// ---------------------------------------------------------------------------
__global__ void __launch_bounds__(256) deg_kernel(const float* __restrict__ a) {
    int warp = (blockIdx.x * 256 + threadIdx.x) >> 5;
    int lane = threadIdx.x & 31;
    const float4* row = (const float4*)(a + (size_t)warp * NNODE);
    float s = 0.f;
#pragma unroll
    for (int j = 0; j < (NNODE / 4) / 32; j++) {
        float4 v = row[lane + j * 32];
        s += v.x + v.y + v.z + v.w;
    }
#pragma unroll
    for (int off = 16; off; off >>= 1) s += __shfl_xor_sync(0xffffffffu, s, off);
    if (lane == 0) g_d[warp] = rsqrtf(s + 1.0f + 1e-8f);
}

// ---------------------------------------------------------------------------
// Kernel: elementwise fp32 -> (bf16 hi, bf16 lo) split
// ---------------------------------------------------------------------------
__global__ void __launch_bounds__(256) split_kernel(const float* __restrict__ s,
                                                    __nv_bfloat16* __restrict__ hi,
                                                    __nv_bfloat16* __restrict__ lo,
                                                    size_t n4) {
    size_t i = (size_t)blockIdx.x * 256 + threadIdx.x;
    if (i >= n4) return;
    float4 v = ((const float4*)s)[i];
    float f[4] = {v.x, v.y, v.z, v.w};
    __nv_bfloat16 h[4], l[4];
#pragma unroll
    for (int k = 0; k < 4; k++) {
        h[k] = __float2bfloat16(f[k]);
        l[k] = __float2bfloat16(f[k] - __bfloat162float(h[k]));
    }
    ((__nv_bfloat162*)hi)[2 * i]     = __nv_bfloat162(h[0], h[1]);
    ((__nv_bfloat162*)hi)[2 * i + 1] = __nv_bfloat162(h[2], h[3]);
    ((__nv_bfloat162*)lo)[2 * i]     = __nv_bfloat162(l[0], l[1]);
    ((__nv_bfloat162*)lo)[2 * i + 1] = __nv_bfloat162(l[2], l[3]);
}

// ---------------------------------------------------------------------------
// Kernel: xt[b,c,j] = d[b,j] * x[b,j,c]  transposed + split into hi/lo
// ---------------------------------------------------------------------------
__global__ void __launch_bounds__(256) split_xt_kernel(const float* __restrict__ x) {
    __shared__ float t[32][33];
    int b  = blockIdx.z;
    int j0 = blockIdx.y * 32;
    int c0 = blockIdx.x * 32;
    int tx = threadIdx.x, ty = threadIdx.y;      // (32, 8)
#pragma unroll
    for (int k = 0; k < 4; k++) {
        int j = j0 + ty + k * 8;
        float dv = g_d[b * NNODE + j];
        t[ty + k * 8][tx] = x[((size_t)(b * NNODE + j)) * IND + c0 + tx] * dv;
    }
    __syncthreads();
#pragma unroll
    for (int k = 0; k < 4; k++) {
        int c = c0 + ty + k * 8;
        int j = j0 + tx;
        float v = t[tx][ty + k * 8];
        __nv_bfloat16 h = __float2bfloat16(v);
        size_t o = ((size_t)b * IND + c) * NNODE + j;
        g_xthi[o] = h;
        g_xtlo[o] = __float2bfloat16(v - __bfloat162float(h));
    }
}

// ---------------------------------------------------------------------------
// Split-bf16 GEMM via mma.sync (HMMA): D[m,n] = sum_k A[m,k]*B[n,k]
//   3-term compensation: Ahi*Bhi + Ahi*Blo + Alo*Bhi  (fp32-equivalent)
// Tile: 128x128, KC=32, double buffer. 8 warps (4 in M x 2 in N), warp 32x64.
// SMEM tiles row-major, row stride 80B (conflict-free STS.128 + ldmatrix).
// EPI: 0 = message passing (d_m scale + d_m^2*x diag, emit hi/lo)
//      1 = bias + relu (emit hi/lo),  2 = bias (emit fp32)
// ---------------------------------------------------------------------------
#define TILE_B 10240        // 128 rows * 80B
#define BUF_B  40960        // 4 tiles
#define GEMM_SMEM 81920     // 2 buffers

template <int KDIM, int EPI, int LDO>
__global__ void __launch_bounds__(256, 2) gemm_k(
    const __nv_bfloat16* __restrict__ Ahi, const __nv_bfloat16* __restrict__ Alo,
    const __nv_bfloat16* __restrict__ Bhi, const __nv_bfloat16* __restrict__ Blo,
    long bstride,
    float* __restrict__ outf,
    __nv_bfloat16* __restrict__ ohi, __nv_bfloat16* __restrict__ olo,
    const float* __restrict__ bias, const float* __restrict__ xdiag)
{
    extern __shared__ char smem_raw[];
    const uint32_t sb  = smem_u32(smem_raw);
    const int tid  = threadIdx.x;
    const int wid  = tid >> 5;
    const int lane = tid & 31;
    const int n0   = blockIdx.x * 128;
    const int m0   = blockIdx.y * 128;
    const int wm   = wid & 3;       // 4 warps in M
    const int wn   = wid >> 2;      // 2 warps in N

    const long batch = bstride ? (long)(m0 >> 10) : 0;
    const __nv_bfloat16* srcs[4] = {Ahi, Alo, Bhi + batch * bstride, Blo + batch * bstride};

    float acc[2][8][4];
#pragma unroll
    for (int i = 0; i < 2; i++)
#pragma unroll
        for (int j = 0; j < 8; j++)
#pragma unroll
            for (int k = 0; k < 4; k++) acc[i][j][k] = 0.f;

    // staging indices: 4 threads per row (16B each), 64 rows per pass
    const int srow = tid >> 2;
    const int sc4  = tid & 3;

    // ldmatrix per-thread base offsets (within a tile)
    const uint32_t a_roff = (uint32_t)((wm * 32 + (lane & 15)) * 80 + ((lane >> 4) * 8) * 2);
    const uint32_t b_roff = (uint32_t)((wn * 64 + ((lane >> 4) << 3) + (lane & 7)) * 80
                                       + (((lane >> 3) & 1) * 8) * 2);

    uint4 pre[8];

    // prologue: chunk 0 -> buffer 0
#pragma unroll
    for (int tile = 0; tile < 4; tile++) {
        const __nv_bfloat16* src = srcs[tile];
        const int rbase = (tile < 2) ? m0 : n0;
#pragma unroll
        for (int rep = 0; rep < 2; rep++)
            pre[tile * 2 + rep] =
                *(const uint4*)(src + (size_t)(rbase + srow + rep * 64) * KDIM + sc4 * 8);
    }
#pragma unroll
    for (int tile = 0; tile < 4; tile++)
#pragma unroll
        for (int rep = 0; rep < 2; rep++) {
            uint32_t so = sb + tile * TILE_B + (srow + rep * 64) * 80 + sc4 * 16;
            uint4 v = pre[tile * 2 + rep];
            asm volatile("st.shared.v4.b32 [%0], {%1,%2,%3,%4};"
                         :: "r"(so), "r"(v.x), "r"(v.y), "r"(v.z), "r"(v.w) : "memory");
        }
    __syncthreads();

    const int NC = KDIM / 32;
    for (int t = 0; t < NC; t++) {
        if (t + 1 < NC) {
            const int kk = (t + 1) * 32;
#pragma unroll
            for (int tile = 0; tile < 4; tile++) {
                const __nv_bfloat16* src = srcs[tile];
                const int rbase = (tile < 2) ? m0 : n0;
#pragma unroll
                for (int rep = 0; rep < 2; rep++)
                    pre[tile * 2 + rep] = *(const uint4*)(
                        src + (size_t)(rbase + srow + rep * 64) * KDIM + kk + sc4 * 8);
            }
        }

        const uint32_t base = sb + (uint32_t)(t & 1) * BUF_B;
#pragma unroll
        for (int ks = 0; ks < 2; ks++) {
            const uint32_t koff = ks * 32;           // 16 bf16 = 32 bytes
            uint32_t ah[2][4], al[2][4];
#pragma unroll
            for (int tm = 0; tm < 2; tm++) {
                ldsm4(base + 0 * TILE_B + a_roff + tm * (16 * 80) + koff, ah[tm]);
                ldsm4(base + 1 * TILE_B + a_roff + tm * (16 * 80) + koff, al[tm]);
            }
#pragma unroll
            for (int tnp = 0; tnp < 4; tnp++) {
                uint32_t bh[4], bl[4];
                ldsm4(base + 2 * TILE_B + b_roff + tnp * (16 * 80) + koff, bh);
                ldsm4(base + 3 * TILE_B + b_roff + tnp * (16 * 80) + koff, bl);
#pragma unroll
                for (int tm = 0; tm < 2; tm++) {
#pragma unroll
                    for (int hf = 0; hf < 2; hf++) {
                        float* c = acc[tm][tnp * 2 + hf];
                        mma16816(c, ah[tm], bh + hf * 2);
                        mma16816(c, ah[tm], bl + hf * 2);
                        mma16816(c, al[tm], bh + hf * 2);
                    }
                }
            }
        }

        if (t + 1 < NC) {
            const uint32_t nb = sb + (uint32_t)((t + 1) & 1) * BUF_B;
#pragma unroll
            for (int tile = 0; tile < 4; tile++)
#pragma unroll
                for (int rep = 0; rep < 2; rep++) {
                    uint32_t so = nb + tile * TILE_B + (srow + rep * 64) * 80 + sc4 * 16;
                    uint4 v = pre[tile * 2 + rep];
                    asm volatile("st.shared.v4.b32 [%0], {%1,%2,%3,%4};"
                                 :: "r"(so), "r"(v.x), "r"(v.y), "r"(v.z), "r"(v.w) : "memory");
                }
        }
        __syncthreads();
    }

    // epilogue: fragment layout -> direct global stores
    // c[0],c[1]: row = base + lane/4,   cols (lane%4)*2 + {0,1}
    // c[2],c[3]: row = base + 8 + lane/4
#pragma unroll
    for (int tm = 0; tm < 2; tm++) {
#pragma unroll
        for (int hf = 0; hf < 2; hf++) {
            const int row = m0 + wm * 32 + tm * 16 + hf * 8 + (lane >> 2);
            float di = 0.f, d2 = 0.f;
            if (EPI == 0) { di = g_d[row]; d2 = di * di; }
#pragma unroll
            for (int tn = 0; tn < 8; tn++) {
                const int col = n0 + wn * 64 + tn * 8 + (lane & 3) * 2;
                float v0 = acc[tm][tn][hf * 2 + 0];
                float v1 = acc[tm][tn][hf * 2 + 1];
                if (EPI == 0) {
                    float2 xv = *(const float2*)(xdiag + (size_t)row * LDO + col);
                    v0 = di * v0 + d2 * xv.x;
                    v1 = di * v1 + d2 * xv.y;
                } else {
                    float2 bv = *(const float2*)(bias + col);
                    v0 += bv.x; v1 += bv.y;
                    if (EPI == 1) { v0 = fmaxf(v0, 0.f); v1 = fmaxf(v1, 0.f); }
                }
                if (EPI == 2) {
                    *(float2*)(outf + (size_t)row * LDO + col) = make_float2(v0, v1);
                } else {
                    __nv_bfloat16 h0 = __float2bfloat16(v0);
                    __nv_bfloat16 h1 = __float2bfloat16(v1);
                    *(__nv_bfloat162*)(ohi + (size_t)row * LDO + col) = __nv_bfloat162(h0, h1);
                    *(__nv_bfloat162*)(olo + (size_t)row * LDO + col) = __nv_bfloat162(
                        __float2bfloat16(v0 - __bfloat162float(h0)),
                        __float2bfloat16(v1 - __bfloat162float(h1)));
                }
            }
        }
    }
}

// ---------------------------------------------------------------------------
extern "C" void kernel_launch(void* const* d_in, const int* in_sizes, int n_in,
                              void* d_out, int out_size) {
    const float* x   = (const float*)d_in[0];
    const float* a   = (const float*)d_in[1];
    const float* W1  = (const float*)d_in[2];
    const float* b1  = (const float*)d_in[3];
    const float* Wmu = (const float*)d_in[4];
    const float* bmu = (const float*)d_in[5];
    const float* Wlv = (const float*)d_in[6];
    const float* blv = (const float*)d_in[7];
    float* out = (float*)d_out;

    cudaFuncSetAttribute(gemm_k<NNODE, 0, IND>,  cudaFuncAttributeMaxDynamicSharedMemorySize, GEMM_SMEM);
    cudaFuncSetAttribute(gemm_k<IND,   1, HIDD>, cudaFuncAttributeMaxDynamicSharedMemorySize, GEMM_SMEM);
    cudaFuncSetAttribute(gemm_k<HIDD,  2, LATD>, cudaFuncAttributeMaxDynamicSharedMemorySize, GEMM_SMEM);

    __nv_bfloat16 *ahi, *alo, *xthi, *xtlo, *hhi, *hlo, *h1hi, *h1lo;
    __nv_bfloat16 *w1hi, *w1lo, *wmuhi, *wmulo, *wlvhi, *wlvlo;
    cudaGetSymbolAddress((void**)&ahi,  g_ahi);  cudaGetSymbolAddress((void**)&alo,  g_alo);
    cudaGetSymbolAddress((void**)&xthi, g_xthi); cudaGetSymbolAddress((void**)&xtlo, g_xtlo);
    cudaGetSymbolAddress((void**)&hhi,  g_hhi);  cudaGetSymbolAddress((void**)&hlo,  g_hlo);
    cudaGetSymbolAddress((void**)&h1hi, g_h1hi); cudaGetSymbolAddress((void**)&h1lo, g_h1lo);
    cudaGetSymbolAddress((void**)&w1hi, g_w1hi); cudaGetSymbolAddress((void**)&w1lo, g_w1lo);
    cudaGetSymbolAddress((void**)&wmuhi, g_wmuhi); cudaGetSymbolAddress((void**)&wmulo, g_wmulo);
    cudaGetSymbolAddress((void**)&wlvhi, g_wlvhi); cudaGetSymbolAddress((void**)&wlvlo, g_wlvlo);

    // 1) degree factors
    deg_kernel<<<TOK / 8, 256>>>(a);

    // 2) operand conversions
    split_kernel<<<(int)(((size_t)BB * NNODE * NNODE / 4) / 256), 256>>>(
        a, ahi, alo, (size_t)BB * NNODE * NNODE / 4);
    split_xt_kernel<<<dim3(IND / 32, NNODE / 32, BB), dim3(32, 8)>>>(x);
    split_kernel<<<(HIDD * IND / 4) / 256, 256>>>(W1, w1hi, w1lo, HIDD * IND / 4);
    split_kernel<<<(LATD * HIDD / 4) / 256, 256>>>(Wmu, wmuhi, wmulo, LATD * HIDD / 4);
    split_kernel<<<(LATD * HIDD / 4) / 256, 256>>>(Wlv, wlvhi, wlvlo, LATD * HIDD / 4);

    // 3) message passing: h = a_norm @ x  (d-scales fused; diagonal in epilogue)
    gemm_k<NNODE, 0, IND><<<dim3(IND / 128, TOK / 128), 256, GEMM_SMEM>>>(
        ahi, alo, xthi, xtlo, (long)IND * NNODE, nullptr, hhi, hlo, nullptr, x);

    // 4) h1 = relu(h @ W1^T + b1)
    gemm_k<IND, 1, HIDD><<<dim3(HIDD / 128, TOK / 128), 256, GEMM_SMEM>>>(
        hhi, hlo, w1hi, w1lo, 0, nullptr, h1hi, h1lo, b1, nullptr);

    // 5) mu / logvar heads
    gemm_k<HIDD, 2, LATD><<<dim3(LATD / 128, TOK / 128), 256, GEMM_SMEM>>>(
        h1hi, h1lo, wmuhi, wmulo, 0, out, nullptr, nullptr, bmu, nullptr);
    gemm_k<HIDD, 2, LATD><<<dim3(LATD / 128, TOK / 128), 256, GEMM_SMEM>>>(
        h1hi, h1lo, wlvhi, wlvlo, 0, out + (size_t)TOK * LATD, nullptr, nullptr, blv, nullptr);
}

// round 4
// speedup vs baseline: 2.6591x; 1.1567x over previous
#include <cuda_runtime.h>
#include <cuda_bf16.h>
#include <cstdint>

#define BB    64
#define NNODE 1024
#define IND   512
#define HIDD  1024
#define LATD  256
#define TOK   (BB * NNODE)   // 65536

// ---------------------------------------------------------------------------
// Scratch (device globals — allocation is forbidden)
// ---------------------------------------------------------------------------
__device__ float g_d[TOK];
__device__ __align__(16) __nv_bfloat16 g_ahi[(size_t)BB * NNODE * NNODE];
__device__ __align__(16) __nv_bfloat16 g_alo[(size_t)BB * NNODE * NNODE];
__device__ __align__(16) __nv_bfloat16 g_xthi[(size_t)BB * IND * NNODE];
__device__ __align__(16) __nv_bfloat16 g_xtlo[(size_t)BB * IND * NNODE];
__device__ __align__(16) __nv_bfloat16 g_hhi[(size_t)TOK * IND];
__device__ __align__(16) __nv_bfloat16 g_hlo[(size_t)TOK * IND];
__device__ __align__(16) __nv_bfloat16 g_h1hi[(size_t)TOK * HIDD];
__device__ __align__(16) __nv_bfloat16 g_h1lo[(size_t)TOK * HIDD];
__device__ __align__(16) __nv_bfloat16 g_w1hi[HIDD * IND],  g_w1lo[HIDD * IND];
__device__ __align__(16) __nv_bfloat16 g_wcathi[2 * LATD * HIDD];   // [Wmu; Wlv]
__device__ __align__(16) __nv_bfloat16 g_wcatlo[2 * LATD * HIDD];

// ---------------------------------------------------------------------------
// helpers (baseline PTX only)
// ---------------------------------------------------------------------------
__device__ __forceinline__ uint32_t smem_u32(const void* p) {
    uint32_t a;
    asm("{ .reg .u64 t; cvta.to.shared.u64 t, %1; cvt.u32.u64 %0, t; }" : "=r"(a) : "l"(p));
    return a;
}
__device__ __forceinline__ void ldsm4(uint32_t addr, uint32_t* r) {
    asm volatile("ldmatrix.sync.aligned.m8n8.x4.shared.b16 {%0,%1,%2,%3}, [%4];"
                 : "=r"(r[0]), "=r"(r[1]), "=r"(r[2]), "=r"(r[3]) : "r"(addr));
}
__device__ __forceinline__ void mma16816(float* c, const uint32_t* a, const uint32_t* b) {
    asm volatile(
        "mma.sync.aligned.m16n8k16.row.col.f32.bf16.bf16.f32 "
        "{%0,%1,%2,%3}, {%4,%5,%6,%7}, {%8,%9}, {%0,%1,%2,%3};"
        : "+f"(c[0]), "+f"(c[1]), "+f"(c[2]), "+f"(c[3])
        : "r"(a[0]), "r"(a[1]), "r"(a[2]), "r"(a[3]), "r"(b[0]), "r"(b[1]));
}
__device__ __forceinline__ void cpasync16(uint32_t dst, const void* src) {
    asm volatile("cp.async.cg.shared.global [%0], [%1], 16;" :: "r"(dst), "l"(src) : "memory");
}
#define CP_COMMIT() asm volatile("cp.async.commit_group;" ::: "memory")
#define CP_WAIT0()  asm volatile("cp.async.wait_group 0;" ::: "memory")

// ---------------------------------------------------------------------------
// Fused: a -> (hi, lo) split AND degree d = rsqrt(rowsum + 1 + 1e-8)
// One warp per row; a read exactly once.
// ---------------------------------------------------------------------------
__global__ void __launch_bounds__(256) dsplit_a_kernel(const float* __restrict__ a) {
    int warp = (blockIdx.x * 256 + threadIdx.x) >> 5;
    int lane = threadIdx.x & 31;
    const float4* row = (const float4*)(a + (size_t)warp * NNODE);
    __nv_bfloat162* hi = (__nv_bfloat162*)(g_ahi + (size_t)warp * NNODE);
    __nv_bfloat162* lo = (__nv_bfloat162*)(g_alo + (size_t)warp * NNODE);
    float s = 0.f;
#pragma unroll
    for (int j = 0; j < 8; j++) {
        int i4 = lane + j * 32;
        float4 v = row[i4];
        s += v.x + v.y + v.z + v.w;
        float f[4] = {v.x, v.y, v.z, v.w};
        __nv_bfloat16 h[4], l[4];
#pragma unroll
        for (int k = 0; k < 4; k++) {
            h[k] = __float2bfloat16(f[k]);
            l[k] = __float2bfloat16(f[k] - __bfloat162float(h[k]));
        }
        hi[2 * i4]     = __nv_bfloat162(h[0], h[1]);
        hi[2 * i4 + 1] = __nv_bfloat162(h[2], h[3]);
        lo[2 * i4]     = __nv_bfloat162(l[0], l[1]);
        lo[2 * i4 + 1] = __nv_bfloat162(l[2], l[3]);
    }
#pragma unroll
    for (int off = 16; off; off >>= 1) s += __shfl_xor_sync(0xffffffffu, s, off);
    if (lane == 0) g_d[warp] = rsqrtf(s + 1.0f + 1e-8f);
}

// ---------------------------------------------------------------------------
// Kernel: elementwise fp32 -> (bf16 hi, bf16 lo) split (for weights)
// ---------------------------------------------------------------------------
__global__ void __launch_bounds__(256) split_kernel(const float* __restrict__ s,
                                                    __nv_bfloat16* __restrict__ hi,
                                                    __nv_bfloat16* __restrict__ lo,
                                                    size_t n4) {
    size_t i = (size_t)blockIdx.x * 256 + threadIdx.x;
    if (i >= n4) return;
    float4 v = ((const float4*)s)[i];
    float f[4] = {v.x, v.y, v.z, v.w};
    __nv_bfloat16 h[4], l[4];
#pragma unroll
    for (int k = 0; k < 4; k++) {
        h[k] = __float2bfloat16(f[k]);
        l[k] = __float2bfloat16(f[k] - __bfloat162float(h[k]));
    }
    ((__nv_bfloat162*)hi)[2 * i]     = __nv_bfloat162(h[0], h[1]);
    ((__nv_bfloat162*)hi)[2 * i + 1] = __nv_bfloat162(h[2], h[3]);
    ((__nv_bfloat162*)lo)[2 * i]     = __nv_bfloat162(l[0], l[1]);
    ((__nv_bfloat162*)lo)[2 * i + 1] = __nv_bfloat162(l[2], l[3]);
}

// ---------------------------------------------------------------------------
// Kernel: xt[b,c,j] = d[b,j] * x[b,j,c]  transposed + split into hi/lo
// ---------------------------------------------------------------------------
__global__ void __launch_bounds__(256) split_xt_kernel(const float* __restrict__ x) {
    __shared__ float t[32][33];
    int b  = blockIdx.z;
    int j0 = blockIdx.y * 32;
    int c0 = blockIdx.x * 32;
    int tx = threadIdx.x, ty = threadIdx.y;      // (32, 8)
#pragma unroll
    for (int k = 0; k < 4; k++) {
        int j = j0 + ty + k * 8;
        float dv = g_d[b * NNODE + j];
        t[ty + k * 8][tx] = x[((size_t)(b * NNODE + j)) * IND + c0 + tx] * dv;
    }
    __syncthreads();
#pragma unroll
    for (int k = 0; k < 4; k++) {
        int c = c0 + ty + k * 8;
        int j = j0 + tx;
        float v = t[tx][ty + k * 8];
        __nv_bfloat16 h = __float2bfloat16(v);
        size_t o = ((size_t)b * IND + c) * NNODE + j;
        g_xthi[o] = h;
        g_xtlo[o] = __float2bfloat16(v - __bfloat162float(h));
    }
}

// ---------------------------------------------------------------------------
// Split-bf16 GEMM via mma.sync (HMMA): D[m,n] = sum_k A[m,k]*B[n,k]
//   3-term compensation: Ahi*Bhi + Ahi*Blo + Alo*Bhi  (fp32-equivalent)
// Tile: 128x128, KC=32, cp.async double buffer, one barrier per chunk.
// 8 warps (4 in M x 2 in N), warp 32x64.
// EPI: 0 = message passing (d_m scale + d_m^2*x diag, emit hi/lo)
//      1 = bias + relu (emit hi/lo)
//      3 = dual-head bias (cols <256 -> mu, >=256 -> logvar), emit fp32
// ---------------------------------------------------------------------------
#define TILE_B 10240        // 128 rows * 80B
#define BUF_B  40960        // 4 tiles
#define GEMM_SMEM 81920     // 2 buffers

template <int KDIM, int EPI, int LDO>
__global__ void __launch_bounds__(256, 2) gemm_k(
    const __nv_bfloat16* __restrict__ Ahi, const __nv_bfloat16* __restrict__ Alo,
    const __nv_bfloat16* __restrict__ Bhi, const __nv_bfloat16* __restrict__ Blo,
    long bstride,
    float* __restrict__ outf,
    __nv_bfloat16* __restrict__ ohi, __nv_bfloat16* __restrict__ olo,
    const float* __restrict__ bias, const float* __restrict__ bias2,
    const float* __restrict__ xdiag)
{
    extern __shared__ char smem_raw[];
    const uint32_t sb  = smem_u32(smem_raw);
    const int tid  = threadIdx.x;
    const int wid  = tid >> 5;
    const int lane = tid & 31;
    const int n0   = blockIdx.x * 128;
    const int m0   = blockIdx.y * 128;
    const int wm   = wid & 3;       // 4 warps in M
    const int wn   = wid >> 2;      // 2 warps in N

    const long batch = bstride ? (long)(m0 >> 10) : 0;
    const __nv_bfloat16* srcs[4] = {Ahi, Alo, Bhi + batch * bstride, Blo + batch * bstride};

    float acc[2][8][4];
#pragma unroll
    for (int i = 0; i < 2; i++)
#pragma unroll
        for (int j = 0; j < 8; j++)
#pragma unroll
            for (int k = 0; k < 4; k++) acc[i][j][k] = 0.f;

    // staging: 4 threads per row (16B each), 64 rows per rep
    const int srow = tid >> 2;
    const int sc4  = tid & 3;

    // per-thread global source row bases (element offsets)
    size_t gsrc[4];
#pragma unroll
    for (int tile = 0; tile < 4; tile++) {
        const int rbase = (tile < 2) ? m0 : n0;
        gsrc[tile] = (size_t)(rbase + srow) * KDIM + sc4 * 8;
    }

    // ldmatrix per-thread base offsets (within a tile)
    const uint32_t a_roff = (uint32_t)((wm * 32 + (lane & 15)) * 80 + ((lane >> 4) * 8) * 2);
    const uint32_t b_roff = (uint32_t)((wn * 64 + ((lane >> 4) << 3) + (lane & 7)) * 80
                                       + (((lane >> 3) & 1) * 8) * 2);

    const int NC = KDIM / 32;

    // prologue: async-stage chunk 0 into buffer 0
#pragma unroll
    for (int tile = 0; tile < 4; tile++)
#pragma unroll
        for (int rep = 0; rep < 2; rep++)
            cpasync16(sb + tile * TILE_B + (srow + rep * 64) * 80 + sc4 * 16,
                      srcs[tile] + gsrc[tile] + (size_t)rep * 64 * KDIM);
    CP_COMMIT();

    for (int t = 0; t < NC; t++) {
        CP_WAIT0();
        __syncthreads();   // chunk t visible to all; all warps done computing t-1

        if (t + 1 < NC) {
            const int kk = (t + 1) * 32;
            const uint32_t nb = sb + (uint32_t)((t + 1) & 1) * BUF_B;
#pragma unroll
            for (int tile = 0; tile < 4; tile++)
#pragma unroll
                for (int rep = 0; rep < 2; rep++)
                    cpasync16(nb + tile * TILE_B + (srow + rep * 64) * 80 + sc4 * 16,
                              srcs[tile] + gsrc[tile] + (size_t)rep * 64 * KDIM + kk);
            CP_COMMIT();
        }

        const uint32_t base = sb + (uint32_t)(t & 1) * BUF_B;
#pragma unroll
        for (int ks = 0; ks < 2; ks++) {
            const uint32_t koff = ks * 32;           // 16 bf16 = 32 bytes
            uint32_t ah[2][4], al[2][4];
#pragma unroll
            for (int tm = 0; tm < 2; tm++) {
                ldsm4(base + 0 * TILE_B + a_roff + tm * (16 * 80) + koff, ah[tm]);
                ldsm4(base + 1 * TILE_B + a_roff + tm * (16 * 80) + koff, al[tm]);
            }
#pragma unroll
            for (int tnp = 0; tnp < 4; tnp++) {
                uint32_t bh[4], bl[4];
                ldsm4(base + 2 * TILE_B + b_roff + tnp * (16 * 80) + koff, bh);
                ldsm4(base + 3 * TILE_B + b_roff + tnp * (16 * 80) + koff, bl);
#pragma unroll
                for (int tm = 0; tm < 2; tm++) {
#pragma unroll
                    for (int hf = 0; hf < 2; hf++) {
                        float* c = acc[tm][tnp * 2 + hf];
                        mma16816(c, ah[tm], bh + hf * 2);
                        mma16816(c, ah[tm], bl + hf * 2);
                        mma16816(c, al[tm], bh + hf * 2);
                    }
                }
            }
        }
    }

    // epilogue: fragment layout -> direct global stores
#pragma unroll
    for (int tm = 0; tm < 2; tm++) {
#pragma unroll
        for (int hf = 0; hf < 2; hf++) {
            const int row = m0 + wm * 32 + tm * 16 + hf * 8 + (lane >> 2);
            float di = 0.f, d2 = 0.f;
            if (EPI == 0) { di = g_d[row]; d2 = di * di; }
#pragma unroll
            for (int tn = 0; tn < 8; tn++) {
                const int col = n0 + wn * 64 + tn * 8 + (lane & 3) * 2;
                float v0 = acc[tm][tn][hf * 2 + 0];
                float v1 = acc[tm][tn][hf * 2 + 1];
                if (EPI == 0) {
                    float2 xv = *(const float2*)(xdiag + (size_t)row * LDO + col);
                    v0 = di * v0 + d2 * xv.x;
                    v1 = di * v1 + d2 * xv.y;
                } else if (EPI == 1) {
                    float2 bv = *(const float2*)(bias + col);
                    v0 = fmaxf(v0 + bv.x, 0.f);
                    v1 = fmaxf(v1 + bv.y, 0.f);
                } else {  // EPI == 3: dual head
                    const float* bp = (col < LATD) ? (bias + col) : (bias2 + col - LATD);
                    float2 bv = *(const float2*)bp;
                    v0 += bv.x; v1 += bv.y;
                }
                if (EPI == 3) {
                    float* dst = (col < LATD)
                        ? (outf + (size_t)row * LATD + col)
                        : (outf + (size_t)TOK * LATD + (size_t)row * LATD + (col - LATD));
                    *(float2*)dst = make_float2(v0, v1);
                } else {
                    __nv_bfloat16 h0 = __float2bfloat16(v0);
                    __nv_bfloat16 h1 = __float2bfloat16(v1);
                    *(__nv_bfloat162*)(ohi + (size_t)row * LDO + col) = __nv_bfloat162(h0, h1);
                    *(__nv_bfloat162*)(olo + (size_t)row * LDO + col) = __nv_bfloat162(
                        __float2bfloat16(v0 - __bfloat162float(h0)),
                        __float2bfloat16(v1 - __bfloat162float(h1)));
                }
            }
        }
    }
}

// ---------------------------------------------------------------------------
extern "C" void kernel_launch(void* const* d_in, const int* in_sizes, int n_in,
                              void* d_out, int out_size) {
    const float* x   = (const float*)d_in[0];
    const float* a   = (const float*)d_in[1];
    const float* W1  = (const float*)d_in[2];
    const float* b1  = (const float*)d_in[3];
    const float* Wmu = (const float*)d_in[4];
    const float* bmu = (const float*)d_in[5];
    const float* Wlv = (const float*)d_in[6];
    const float* blv = (const float*)d_in[7];
    float* out = (float*)d_out;

    cudaFuncSetAttribute(gemm_k<NNODE, 0, IND>,  cudaFuncAttributeMaxDynamicSharedMemorySize, GEMM_SMEM);
    cudaFuncSetAttribute(gemm_k<IND,   1, HIDD>, cudaFuncAttributeMaxDynamicSharedMemorySize, GEMM_SMEM);
    cudaFuncSetAttribute(gemm_k<HIDD,  3, LATD>, cudaFuncAttributeMaxDynamicSharedMemorySize, GEMM_SMEM);

    __nv_bfloat16 *ahi, *alo, *xthi, *xtlo, *hhi, *hlo, *h1hi, *h1lo;
    __nv_bfloat16 *w1hi, *w1lo, *wchi, *wclo;
    cudaGetSymbolAddress((void**)&ahi,  g_ahi);  cudaGetSymbolAddress((void**)&alo,  g_alo);
    cudaGetSymbolAddress((void**)&xthi, g_xthi); cudaGetSymbolAddress((void**)&xtlo, g_xtlo);
    cudaGetSymbolAddress((void**)&hhi,  g_hhi);  cudaGetSymbolAddress((void**)&hlo,  g_hlo);
    cudaGetSymbolAddress((void**)&h1hi, g_h1hi); cudaGetSymbolAddress((void**)&h1lo, g_h1lo);
    cudaGetSymbolAddress((void**)&w1hi, g_w1hi); cudaGetSymbolAddress((void**)&w1lo, g_w1lo);
    cudaGetSymbolAddress((void**)&wchi, g_wcathi); cudaGetSymbolAddress((void**)&wclo, g_wcatlo);

    // 1) fused adjacency split + degree factors (a read once)
    dsplit_a_kernel<<<TOK / 8, 256>>>(a);

    // 2) remaining operand conversions
    split_xt_kernel<<<dim3(IND / 32, NNODE / 32, BB), dim3(32, 8)>>>(x);
    split_kernel<<<(HIDD * IND / 4) / 256, 256>>>(W1, w1hi, w1lo, HIDD * IND / 4);
    split_kernel<<<(LATD * HIDD / 4) / 256, 256>>>(Wmu, wchi, wclo, LATD * HIDD / 4);
    split_kernel<<<(LATD * HIDD / 4) / 256, 256>>>(
        Wlv, wchi + (size_t)LATD * HIDD, wclo + (size_t)LATD * HIDD, LATD * HIDD / 4);

    // 3) message passing: h = a_norm @ x  (d-scales fused; diagonal in epilogue)
    gemm_k<NNODE, 0, IND><<<dim3(IND / 128, TOK / 128), 256, GEMM_SMEM>>>(
        ahi, alo, xthi, xtlo, (long)IND * NNODE, nullptr, hhi, hlo, nullptr, nullptr, x);

    // 4) h1 = relu(h @ W1^T + b1)
    gemm_k<IND, 1, HIDD><<<dim3(HIDD / 128, TOK / 128), 256, GEMM_SMEM>>>(
        hhi, hlo, w1hi, w1lo, 0, nullptr, h1hi, h1lo, b1, nullptr, nullptr);

    // 5) fused mu+logvar heads: one N=512 GEMM over [Wmu; Wlv]
    gemm_k<HIDD, 3, LATD><<<dim3((2 * LATD) / 128, TOK / 128), 256, GEMM_SMEM>>>(
        h1hi, h1lo, wchi, wclo, 0, out, nullptr, nullptr, bmu, blv, nullptr);
}

// round 5
// speedup vs baseline: 2.6873x; 1.0106x over previous
#include <cuda_runtime.h>
#include <cuda_bf16.h>
#include <cstdint>

#define BB    64
#define NNODE 1024
#define IND   512
#define HIDD  1024
#define LATD  256
#define TOK   (BB * NNODE)   // 65536

// ---------------------------------------------------------------------------
// Scratch (device globals — allocation is forbidden)
// ---------------------------------------------------------------------------
__device__ float g_d[TOK];
__device__ __align__(16) __nv_bfloat16 g_ahi[(size_t)BB * NNODE * NNODE];
__device__ __align__(16) __nv_bfloat16 g_alo[(size_t)BB * NNODE * NNODE];
__device__ __align__(16) __nv_bfloat16 g_xthi[(size_t)BB * IND * NNODE];
__device__ __align__(16) __nv_bfloat16 g_xtlo[(size_t)BB * IND * NNODE];
__device__ __align__(16) __nv_bfloat16 g_hhi[(size_t)TOK * IND];
__device__ __align__(16) __nv_bfloat16 g_hlo[(size_t)TOK * IND];
__device__ __align__(16) __nv_bfloat16 g_h1hi[(size_t)TOK * HIDD];
__device__ __align__(16) __nv_bfloat16 g_h1lo[(size_t)TOK * HIDD];
__device__ __align__(16) __nv_bfloat16 g_w1hi[HIDD * IND],  g_w1lo[HIDD * IND];
__device__ __align__(16) __nv_bfloat16 g_wcathi[2 * LATD * HIDD];   // [Wmu; Wlv]
__device__ __align__(16) __nv_bfloat16 g_wcatlo[2 * LATD * HIDD];

// ---------------------------------------------------------------------------
// helpers (baseline PTX only)
// ---------------------------------------------------------------------------
__device__ __forceinline__ uint32_t smem_u32(const void* p) {
    uint32_t a;
    asm("{ .reg .u64 t; cvta.to.shared.u64 t, %1; cvt.u32.u64 %0, t; }" : "=r"(a) : "l"(p));
    return a;
}
__device__ __forceinline__ void ldsm4(uint32_t addr, uint32_t* r) {
    asm volatile("ldmatrix.sync.aligned.m8n8.x4.shared.b16 {%0,%1,%2,%3}, [%4];"
                 : "=r"(r[0]), "=r"(r[1]), "=r"(r[2]), "=r"(r[3]) : "r"(addr));
}
__device__ __forceinline__ void mma16816(float* c, const uint32_t* a, const uint32_t* b) {
    asm volatile(
        "mma.sync.aligned.m16n8k16.row.col.f32.bf16.bf16.f32 "
        "{%0,%1,%2,%3}, {%4,%5,%6,%7}, {%8,%9}, {%0,%1,%2,%3};"
        : "+f"(c[0]), "+f"(c[1]), "+f"(c[2]), "+f"(c[3])
        : "r"(a[0]), "r"(a[1]), "r"(a[2]), "r"(a[3]), "r"(b[0]), "r"(b[1]));
}
__device__ __forceinline__ void cpasync16(uint32_t dst, const void* src) {
    asm volatile("cp.async.cg.shared.global [%0], [%1], 16;" :: "r"(dst), "l"(src) : "memory");
}
#define CP_COMMIT() asm volatile("cp.async.commit_group;" ::: "memory")
#define CP_WAIT0()  asm volatile("cp.async.wait_group 0;" ::: "memory")

// ---------------------------------------------------------------------------
// Fused: a -> (hi, lo) split AND degree d = rsqrt(rowsum + 1 + 1e-8)
// ---------------------------------------------------------------------------
__global__ void __launch_bounds__(256) dsplit_a_kernel(const float* __restrict__ a) {
    int warp = (blockIdx.x * 256 + threadIdx.x) >> 5;
    int lane = threadIdx.x & 31;
    const float4* row = (const float4*)(a + (size_t)warp * NNODE);
    __nv_bfloat162* hi = (__nv_bfloat162*)(g_ahi + (size_t)warp * NNODE);
    __nv_bfloat162* lo = (__nv_bfloat162*)(g_alo + (size_t)warp * NNODE);
    float s = 0.f;
#pragma unroll
    for (int j = 0; j < 8; j++) {
        int i4 = lane + j * 32;
        float4 v = row[i4];
        s += v.x + v.y + v.z + v.w;
        float f[4] = {v.x, v.y, v.z, v.w};
        __nv_bfloat16 h[4], l[4];
#pragma unroll
        for (int k = 0; k < 4; k++) {
            h[k] = __float2bfloat16(f[k]);
            l[k] = __float2bfloat16(f[k] - __bfloat162float(h[k]));
        }
        hi[2 * i4]     = __nv_bfloat162(h[0], h[1]);
        hi[2 * i4 + 1] = __nv_bfloat162(h[2], h[3]);
        lo[2 * i4]     = __nv_bfloat162(l[0], l[1]);
        lo[2 * i4 + 1] = __nv_bfloat162(l[2], l[3]);
    }
#pragma unroll
    for (int off = 16; off; off >>= 1) s += __shfl_xor_sync(0xffffffffu, s, off);
    if (lane == 0) g_d[warp] = rsqrtf(s + 1.0f + 1e-8f);
}

// ---------------------------------------------------------------------------
// Kernel: xt[b,c,j] = d[b,j] * x[b,j,c]  transposed + split into hi/lo
// ---------------------------------------------------------------------------
__global__ void __launch_bounds__(256) split_xt_kernel(const float* __restrict__ x) {
    __shared__ float t[32][33];
    int b  = blockIdx.z;
    int j0 = blockIdx.y * 32;
    int c0 = blockIdx.x * 32;
    int tx = threadIdx.x, ty = threadIdx.y;      // (32, 8)
#pragma unroll
    for (int k = 0; k < 4; k++) {
        int j = j0 + ty + k * 8;
        float dv = g_d[b * NNODE + j];
        t[ty + k * 8][tx] = x[((size_t)(b * NNODE + j)) * IND + c0 + tx] * dv;
    }
    __syncthreads();
#pragma unroll
    for (int k = 0; k < 4; k++) {
        int c = c0 + ty + k * 8;
        int j = j0 + tx;
        float v = t[tx][ty + k * 8];
        __nv_bfloat16 h = __float2bfloat16(v);
        size_t o = ((size_t)b * IND + c) * NNODE + j;
        g_xthi[o] = h;
        g_xtlo[o] = __float2bfloat16(v - __bfloat162float(h));
    }
}

// ---------------------------------------------------------------------------
// All weight splits in one kernel: W1, Wmu->wcat[0:], Wlv->wcat[LATD*HIDD:]
// ---------------------------------------------------------------------------
#define W1_F4   (HIDD * IND / 4)          // 131072
#define WHD_F4  (LATD * HIDD / 4)         // 65536
__global__ void __launch_bounds__(256) split_w_kernel(const float* __restrict__ W1,
                                                      const float* __restrict__ Wmu,
                                                      const float* __restrict__ Wlv) {
    size_t i = (size_t)blockIdx.x * 256 + threadIdx.x;
    const float* src; __nv_bfloat16 *hi, *lo; size_t o;
    if (i < W1_F4)                 { src = W1;  hi = g_w1hi;  lo = g_w1lo;  o = i; }
    else if (i < W1_F4 + WHD_F4)   { src = Wmu; hi = g_wcathi; lo = g_wcatlo; o = i - W1_F4; }
    else                           { src = Wlv; hi = g_wcathi + (size_t)LATD * HIDD;
                                     lo = g_wcatlo + (size_t)LATD * HIDD; o = i - W1_F4 - WHD_F4; }
    float4 v = ((const float4*)src)[o];
    float f[4] = {v.x, v.y, v.z, v.w};
    __nv_bfloat16 h[4], l[4];
#pragma unroll
    for (int k = 0; k < 4; k++) {
        h[k] = __float2bfloat16(f[k]);
        l[k] = __float2bfloat16(f[k] - __bfloat162float(h[k]));
    }
    ((__nv_bfloat162*)hi)[2 * o]     = __nv_bfloat162(h[0], h[1]);
    ((__nv_bfloat162*)hi)[2 * o + 1] = __nv_bfloat162(h[2], h[3]);
    ((__nv_bfloat162*)lo)[2 * o]     = __nv_bfloat162(l[0], l[1]);
    ((__nv_bfloat162*)lo)[2 * o + 1] = __nv_bfloat162(l[2], l[3]);
}

// ---------------------------------------------------------------------------
// Split-bf16 GEMM via mma.sync (HMMA): D[m,n] = sum_k A[m,k]*B[n,k]
//   3-term compensation: Ahi*Bhi + Ahi*Blo + Alo*Bhi  (fp32-equivalent)
// Tile: 128x128, KC=32, cp.async double buffer, one barrier per chunk.
// EPI: 0 = message passing (d_m scale + d_m^2*x diag, emit hi/lo via smem restage)
//      1 = bias + relu (emit hi/lo via smem restage)
//      3 = dual-head bias (cols <256 -> mu, >=256 -> logvar), emit fp32
// ---------------------------------------------------------------------------
#define TILE_B 10240        // 128 rows * 80B
#define BUF_B  40960        // 4 tiles
#define GEMM_SMEM 81920     // 2 buffers
#define STG_STRIDE 272      // bytes: (128+8) bf16 per row

template <int KDIM, int EPI, int LDO>
__global__ void __launch_bounds__(256, 2) gemm_k(
    const __nv_bfloat16* __restrict__ Ahi, const __nv_bfloat16* __restrict__ Alo,
    const __nv_bfloat16* __restrict__ Bhi, const __nv_bfloat16* __restrict__ Blo,
    long bstride,
    float* __restrict__ outf,
    __nv_bfloat16* __restrict__ ohi, __nv_bfloat16* __restrict__ olo,
    const float* __restrict__ bias, const float* __restrict__ bias2,
    const float* __restrict__ xdiag)
{
    extern __shared__ char smem_raw[];
    const uint32_t sb  = smem_u32(smem_raw);
    const int tid  = threadIdx.x;
    const int wid  = tid >> 5;
    const int lane = tid & 31;
    const int n0   = blockIdx.x * 128;
    const int m0   = blockIdx.y * 128;
    const int wm   = wid & 3;       // 4 warps in M
    const int wn   = wid >> 2;      // 2 warps in N

    const long batch = bstride ? (long)(m0 >> 10) : 0;
    const __nv_bfloat16* srcs[4] = {Ahi, Alo, Bhi + batch * bstride, Blo + batch * bstride};

    float acc[2][8][4];
#pragma unroll
    for (int i = 0; i < 2; i++)
#pragma unroll
        for (int j = 0; j < 8; j++)
#pragma unroll
            for (int k = 0; k < 4; k++) acc[i][j][k] = 0.f;

    const int srow = tid >> 2;
    const int sc4  = tid & 3;

    size_t gsrc[4];
#pragma unroll
    for (int tile = 0; tile < 4; tile++) {
        const int rbase = (tile < 2) ? m0 : n0;
        gsrc[tile] = (size_t)(rbase + srow) * KDIM + sc4 * 8;
    }

    const uint32_t a_roff = (uint32_t)((wm * 32 + (lane & 15)) * 80 + ((lane >> 4) * 8) * 2);
    const uint32_t b_roff = (uint32_t)((wn * 64 + ((lane >> 4) << 3) + (lane & 7)) * 80
                                       + (((lane >> 3) & 1) * 8) * 2);

    const int NC = KDIM / 32;

#pragma unroll
    for (int tile = 0; tile < 4; tile++)
#pragma unroll
        for (int rep = 0; rep < 2; rep++)
            cpasync16(sb + tile * TILE_B + (srow + rep * 64) * 80 + sc4 * 16,
                      srcs[tile] + gsrc[tile] + (size_t)rep * 64 * KDIM);
    CP_COMMIT();

    for (int t = 0; t < NC; t++) {
        CP_WAIT0();
        __syncthreads();

        if (t + 1 < NC) {
            const int kk = (t + 1) * 32;
            const uint32_t nb = sb + (uint32_t)((t + 1) & 1) * BUF_B;
#pragma unroll
            for (int tile = 0; tile < 4; tile++)
#pragma unroll
                for (int rep = 0; rep < 2; rep++)
                    cpasync16(nb + tile * TILE_B + (srow + rep * 64) * 80 + sc4 * 16,
                              srcs[tile] + gsrc[tile] + (size_t)rep * 64 * KDIM + kk);
            CP_COMMIT();
        }

        const uint32_t base = sb + (uint32_t)(t & 1) * BUF_B;
#pragma unroll
        for (int ks = 0; ks < 2; ks++) {
            const uint32_t koff = ks * 32;
            uint32_t ah[2][4], al[2][4];
#pragma unroll
            for (int tm = 0; tm < 2; tm++) {
                ldsm4(base + 0 * TILE_B + a_roff + tm * (16 * 80) + koff, ah[tm]);
                ldsm4(base + 1 * TILE_B + a_roff + tm * (16 * 80) + koff, al[tm]);
            }
#pragma unroll
            for (int tnp = 0; tnp < 4; tnp++) {
                uint32_t bh[4], bl[4];
                ldsm4(base + 2 * TILE_B + b_roff + tnp * (16 * 80) + koff, bh);
                ldsm4(base + 3 * TILE_B + b_roff + tnp * (16 * 80) + koff, bl);
#pragma unroll
                for (int tm = 0; tm < 2; tm++) {
#pragma unroll
                    for (int hf = 0; hf < 2; hf++) {
                        float* c = acc[tm][tnp * 2 + hf];
                        mma16816(c, ah[tm], bh + hf * 2);
                        mma16816(c, ah[tm], bl + hf * 2);
                        mma16816(c, al[tm], bh + hf * 2);
                    }
                }
            }
        }
    }

    if (EPI == 3) {
        // direct fp32 dual-head stores (float2 already coalesces well)
#pragma unroll
        for (int tm = 0; tm < 2; tm++)
#pragma unroll
            for (int hf = 0; hf < 2; hf++) {
                const int row = m0 + wm * 32 + tm * 16 + hf * 8 + (lane >> 2);
#pragma unroll
                for (int tn = 0; tn < 8; tn++) {
                    const int col = n0 + wn * 64 + tn * 8 + (lane & 3) * 2;
                    float v0 = acc[tm][tn][hf * 2 + 0];
                    float v1 = acc[tm][tn][hf * 2 + 1];
                    const float* bp = (col < LATD) ? (bias + col) : (bias2 + col - LATD);
                    float2 bv = *(const float2*)bp;
                    v0 += bv.x; v1 += bv.y;
                    float* dst = (col < LATD)
                        ? (outf + (size_t)row * LATD + col)
                        : (outf + (size_t)TOK * LATD + (size_t)row * LATD + (col - LATD));
                    *(float2*)dst = make_float2(v0, v1);
                }
            }
        return;
    }

    // EPI 0/1: apply epilogue math, restage hi/lo through SMEM, wide stores
    __syncthreads();   // mainloop reads of smem done before overwrite
    char* hi_st = smem_raw;                    // 128 * 272B = 34816
    char* lo_st = smem_raw + 40960;
#pragma unroll
    for (int tm = 0; tm < 2; tm++) {
#pragma unroll
        for (int hf = 0; hf < 2; hf++) {
            const int rl = wm * 32 + tm * 16 + hf * 8 + (lane >> 2);
            const int row = m0 + rl;
            float di = 0.f, d2 = 0.f;
            if (EPI == 0) { di = g_d[row]; d2 = di * di; }
#pragma unroll
            for (int tn = 0; tn < 8; tn++) {
                const int cl = wn * 64 + tn * 8 + (lane & 3) * 2;
                float v0 = acc[tm][tn][hf * 2 + 0];
                float v1 = acc[tm][tn][hf * 2 + 1];
                if (EPI == 0) {
                    float2 xv = *(const float2*)(xdiag + (size_t)row * LDO + n0 + cl);
                    v0 = di * v0 + d2 * xv.x;
                    v1 = di * v1 + d2 * xv.y;
                } else {
                    float2 bv = *(const float2*)(bias + n0 + cl);
                    v0 = fmaxf(v0 + bv.x, 0.f);
                    v1 = fmaxf(v1 + bv.y, 0.f);
                }
                __nv_bfloat16 h0 = __float2bfloat16(v0);
                __nv_bfloat16 h1 = __float2bfloat16(v1);
                *(__nv_bfloat162*)(hi_st + rl * STG_STRIDE + cl * 2) = __nv_bfloat162(h0, h1);
                *(__nv_bfloat162*)(lo_st + rl * STG_STRIDE + cl * 2) = __nv_bfloat162(
                    __float2bfloat16(v0 - __bfloat162float(h0)),
                    __float2bfloat16(v1 - __bfloat162float(h1)));
            }
        }
    }
    __syncthreads();
#pragma unroll
    for (int it = 0; it < 8; it++) {
        int lin = it * 256 + tid;        // 0..2047
        int r   = lin >> 4;              // 0..127
        int c16 = lin & 15;              // 16B segment
        uint4 vh = *(uint4*)(hi_st + r * STG_STRIDE + c16 * 16);
        uint4 vl = *(uint4*)(lo_st + r * STG_STRIDE + c16 * 16);
        size_t go = (size_t)(m0 + r) * LDO + n0 + c16 * 8;
        *(uint4*)(ohi + go) = vh;
        *(uint4*)(olo + go) = vl;
    }
}

// ---------------------------------------------------------------------------
extern "C" void kernel_launch(void* const* d_in, const int* in_sizes, int n_in,
                              void* d_out, int out_size) {
    const float* x   = (const float*)d_in[0];
    const float* a   = (const float*)d_in[1];
    const float* W1  = (const float*)d_in[2];
    const float* b1  = (const float*)d_in[3];
    const float* Wmu = (const float*)d_in[4];
    const float* bmu = (const float*)d_in[5];
    const float* Wlv = (const float*)d_in[6];
    const float* blv = (const float*)d_in[7];
    float* out = (float*)d_out;

    cudaFuncSetAttribute(gemm_k<NNODE, 0, IND>,  cudaFuncAttributeMaxDynamicSharedMemorySize, GEMM_SMEM);
    cudaFuncSetAttribute(gemm_k<IND,   1, HIDD>, cudaFuncAttributeMaxDynamicSharedMemorySize, GEMM_SMEM);
    cudaFuncSetAttribute(gemm_k<HIDD,  3, LATD>, cudaFuncAttributeMaxDynamicSharedMemorySize, GEMM_SMEM);

    __nv_bfloat16 *ahi, *alo, *xthi, *xtlo, *hhi, *hlo, *h1hi, *h1lo;
    __nv_bfloat16 *w1hi, *w1lo, *wchi, *wclo;
    cudaGetSymbolAddress((void**)&ahi,  g_ahi);  cudaGetSymbolAddress((void**)&alo,  g_alo);
    cudaGetSymbolAddress((void**)&xthi, g_xthi); cudaGetSymbolAddress((void**)&xtlo, g_xtlo);
    cudaGetSymbolAddress((void**)&hhi,  g_hhi);  cudaGetSymbolAddress((void**)&hlo,  g_hlo);
    cudaGetSymbolAddress((void**)&h1hi, g_h1hi); cudaGetSymbolAddress((void**)&h1lo, g_h1lo);
    cudaGetSymbolAddress((void**)&w1hi, g_w1hi); cudaGetSymbolAddress((void**)&w1lo, g_w1lo);
    cudaGetSymbolAddress((void**)&wchi, g_wcathi); cudaGetSymbolAddress((void**)&wclo, g_wcatlo);

    // #1 fused adjacency split + degree factors
    dsplit_a_kernel<<<TOK / 8, 256>>>(a);
    // #2 x transpose + d_j scale + split
    split_xt_kernel<<<dim3(IND / 32, NNODE / 32, BB), dim3(32, 8)>>>(x);
    // #3 all weight splits
    split_w_kernel<<<(W1_F4 + 2 * WHD_F4) / 256, 256>>>(W1, Wmu, Wlv);
    // #4 message passing GEMM (profiled launch)
    gemm_k<NNODE, 0, IND><<<dim3(IND / 128, TOK / 128), 256, GEMM_SMEM>>>(
        ahi, alo, xthi, xtlo, (long)IND * NNODE, nullptr, hhi, hlo, nullptr, nullptr, x);
    // #5 h1 = relu(h @ W1^T + b1)
    gemm_k<IND, 1, HIDD><<<dim3(HIDD / 128, TOK / 128), 256, GEMM_SMEM>>>(
        hhi, hlo, w1hi, w1lo, 0, nullptr, h1hi, h1lo, b1, nullptr, nullptr);
    // #6 fused mu+logvar heads: one N=512 GEMM over [Wmu; Wlv]
    gemm_k<HIDD, 3, LATD><<<dim3((2 * LATD) / 128, TOK / 128), 256, GEMM_SMEM>>>(
        h1hi, h1lo, wchi, wclo, 0, out, nullptr, nullptr, bmu, blv, nullptr);
}